// round 12
// baseline (speedup 1.0000x reference)
#include <cuda_runtime.h>
#include <cuda_fp16.h>
#include <cstdint>

// DynamicHybridRouter via mma.sync fp16 3-product split GEMM.
// logits = x[M,2048] @ W^T[2048,64] + b; all-mature -> top-2 softmax scatter,
// any-immature -> softmax(logits/2).
//
// Precision: a = hi + lo/2048, hi = f16_rn(a), lo = f16_rn((a-hi)*2048).
// acc1 += ahi*bhi ; acc2 += ahi*blo + alo*bhi ; logits = acc1 + acc2/2048.
// Dropped lo*lo ~2^-24 rel -> logit err ~2e-7.
//
// R11: wavefront-bound fix. A staged through SMEM (coalesced LDG.128 ->
// cvt -> STS -> ldmatrix.x4), warps repartitioned 4M x 2N x 2K to halve
// B-fragment wavefronts. Per-tile L1tex wavefronts 1024 -> ~384.

constexpr int KD = 2048;
constexpr int NEXP = 64;
constexpr int BM = 128;
constexpr int NT = KD / 32;          // 64 k-tiles
constexpr int LGS = 68;
constexpr float TEMP_INV = 0.5f;
constexpr float LO_SCALE = 2048.0f;
constexpr float LO_INV = 1.0f / 2048.0f;

constexpr int ASTR = 80;                  // A smem row stride (bank-safe)
constexpr int HALF_OFF = BM * ASTR;       // 10240 (lo plane offset)
constexpr int STAGE = 2 * HALF_OFF;       // 20480 per stage (hi+lo)
constexpr int SMEM_BYTES = 2 * STAGE + 256;   // 41216 (logits overlay stage0)

// [k16=128][e=64][fc=4] -> uint4 {hi(k=2fc,2fc+1), hi(2fc+8,2fc+9),
//                                 lo(2fc,2fc+1),   lo(2fc+8,2fc+9)}
__device__ uint4 g_wpack[128 * 64 * 4];

__device__ __forceinline__ uint32_t h2u(__half2 h) {
    return *reinterpret_cast<uint32_t*>(&h);
}

__global__ void __launch_bounds__(256) pack_w_kernel(const float* __restrict__ gw) {
    int i = blockIdx.x * 256 + threadIdx.x;     // 32768 items
    int fc = i & 3, e = (i >> 2) & 63, k16 = i >> 8;
    const float* p = gw + e * KD + k16 * 16 + 2 * fc;
    float2 v0 = make_float2(p[0], p[1]);
    float2 v8 = make_float2(p[8], p[9]);
    __half2 h0 = __float22half2_rn(v0);
    __half2 h8 = __float22half2_rn(v8);
    float2 f0 = __half22float2(h0);
    float2 f8 = __half22float2(h8);
    __half2 l0 = __float22half2_rn(
        make_float2((v0.x - f0.x) * LO_SCALE, (v0.y - f0.y) * LO_SCALE));
    __half2 l8 = __float22half2_rn(
        make_float2((v8.x - f8.x) * LO_SCALE, (v8.y - f8.y) * LO_SCALE));
    uint4 q;
    q.x = h2u(h0); q.y = h2u(h8); q.z = h2u(l0); q.w = h2u(l8);
    g_wpack[i] = q;
}

__device__ __forceinline__ void mma16(float* d, const uint32_t* a,
                                      uint32_t b0, uint32_t b1) {
    asm volatile(
        "mma.sync.aligned.m16n8k16.row.col.f32.f16.f16.f32 "
        "{%0,%1,%2,%3}, {%4,%5,%6,%7}, {%8,%9}, {%0,%1,%2,%3};"
        : "+f"(d[0]), "+f"(d[1]), "+f"(d[2]), "+f"(d[3])
        : "r"(a[0]), "r"(a[1]), "r"(a[2]), "r"(a[3]), "r"(b0), "r"(b1));
}

__device__ __forceinline__ void ldm4(uint32_t* r, uint32_t a) {
    asm volatile(
        "ldmatrix.sync.aligned.m8n8.x4.shared.b16 {%0,%1,%2,%3}, [%4];"
        : "=r"(r[0]), "=r"(r[1]), "=r"(r[2]), "=r"(r[3]) : "r"(a));
}

// convert one float4 row-chunk to hi/lo halves and store to stage sp
__device__ __forceinline__ void sts_tile(char* sp, float4 v, int row, int kq) {
    __half2 h01 = __float22half2_rn(make_float2(v.x, v.y));
    __half2 h23 = __float22half2_rn(make_float2(v.z, v.w));
    float2 f01 = __half22float2(h01);
    float2 f23 = __half22float2(h23);
    __half2 l01 = __float22half2_rn(
        make_float2((v.x - f01.x) * LO_SCALE, (v.y - f01.y) * LO_SCALE));
    __half2 l23 = __float22half2_rn(
        make_float2((v.z - f23.x) * LO_SCALE, (v.w - f23.y) * LO_SCALE));
    *(uint2*)(sp + row * ASTR + kq * 8) = make_uint2(h2u(h01), h2u(h23));
    *(uint2*)(sp + HALF_OFF + row * ASTR + kq * 8) =
        make_uint2(h2u(l01), h2u(l23));
}

__global__ void __launch_bounds__(512, 1)
router_fp16(const float* __restrict__ x,
            const float* __restrict__ gb,
            const int*   __restrict__ mat,
            float*       __restrict__ out)
{
    __shared__ __align__(16) char smp[SMEM_BYTES];
    float* lg = (float*)smp;                    // epilogue overlay
    float* sbias = (float*)(smp + 2 * STAGE);   // outside stages

    const int tid = threadIdx.x;
    const int w   = tid >> 5;
    const int l   = tid & 31;
    const int fr  = l >> 2;           // fragment row / B n-in-group
    const int fc  = l & 3;            // fragment k quad
    const int ms  = w & 3;            // M slice (32 rows)
    const int nh  = (w >> 2) & 1;     // expert half (32 experts)
    const int kg  = w >> 3;           // k16 half of the 32-k tile
    const int blockRow = blockIdx.x * BM;

    int imm = 0;
    if (tid < NEXP) {
        imm = (mat[tid] == 0) ? 1 : 0;
        sbias[tid] = gb[tid];
    }
    const int anyImm = __syncthreads_or(imm);

    float acc1[2][4][4], acc2[2][4][4];
#pragma unroll
    for (int mt = 0; mt < 2; ++mt)
#pragma unroll
        for (int nt = 0; nt < 4; ++nt)
#pragma unroll
            for (int q = 0; q < 4; ++q) {
                acc1[mt][nt][q] = 0.f;
                acc2[mt][nt][q] = 0.f;
            }

    // ---- ldmatrix lane addresses (stage 0; add STAGE for stage 1) ----
    uint32_t smem_base = (uint32_t)__cvta_generic_to_shared(smp);
    uint32_t abase[2];
#pragma unroll
    for (int mt = 0; mt < 2; ++mt) {
        int arow = ms * 32 + mt * 16 + (l & 7) + ((l >> 3) & 1) * 8;
        int akoff = kg * 32 + (l >> 4) * 16;
        abase[mt] = smem_base + arow * ASTR + akoff;
    }

    // ---- A gmem mapping: thread covers rows (tid>>3) and +64, 16B chunk ----
    const int row0 = tid >> 3, kq = tid & 7;
    const float* xg = x + (size_t)(blockRow + row0) * KD + kq * 4;

    // ---- prologue: tile 0 -> stage 0; tile 1 -> regs ----
    float4 av0 = *(const float4*)(xg);
    float4 av1 = *(const float4*)(xg + (size_t)64 * KD);
    sts_tile(smp, av0, row0, kq);
    sts_tile(smp, av1, row0 + 64, kq);
    av0 = *(const float4*)(xg + 32);
    av1 = *(const float4*)(xg + (size_t)64 * KD + 32);
    __syncthreads();

    const uint4* wbase = g_wpack + nh * 128 + fr * 4 + fc;

    for (int kt = 0; kt < NT; ++kt) {
        const int s = kt & 1;

        // ---- STS tile kt+1 (data ldg'd at kt-1), then LDG tile kt+2 ----
        if (kt + 1 < NT) {
            char* spn = smp + ((kt + 1) & 1) * STAGE;
            sts_tile(spn, av0, row0, kq);
            sts_tile(spn, av1, row0 + 64, kq);
        }
        if (kt + 2 < NT) {
            av0 = *(const float4*)(xg + (kt + 2) * 32);
            av1 = *(const float4*)(xg + (size_t)64 * KD + (kt + 2) * 32);
        }

        // ---- B fragments (L1-resident wpack) ----
        const uint4* wt = wbase + (size_t)(kt * 2 + kg) * 256;
        uint4 bq[4];
#pragma unroll
        for (int nt = 0; nt < 4; ++nt) bq[nt] = __ldg(wt + nt * 32);

        // ---- A fragments from stage s ----
        uint32_t ahi[2][4], alo[2][4];
#pragma unroll
        for (int mt = 0; mt < 2; ++mt) {
            uint32_t a = abase[mt] + s * STAGE;
            ldm4(ahi[mt], a);
            ldm4(alo[mt], a + HALF_OFF);
        }

        // ---- 24 mma, product-major (8 independent per group) ----
#pragma unroll
        for (int nt = 0; nt < 4; ++nt)
#pragma unroll
            for (int mt = 0; mt < 2; ++mt)
                mma16(acc1[mt][nt], ahi[mt], bq[nt].x, bq[nt].y);
#pragma unroll
        for (int nt = 0; nt < 4; ++nt)
#pragma unroll
            for (int mt = 0; mt < 2; ++mt)
                mma16(acc2[mt][nt], ahi[mt], bq[nt].z, bq[nt].w);
#pragma unroll
        for (int nt = 0; nt < 4; ++nt)
#pragma unroll
            for (int mt = 0; mt < 2; ++mt)
                mma16(acc2[mt][nt], alo[mt], bq[nt].x, bq[nt].y);

        __syncthreads();
    }

    // ---- k-split reduction into logits SMEM (overlays stages) ----
    if (kg == 1) {
#pragma unroll
        for (int mt = 0; mt < 2; ++mt)
#pragma unroll
            for (int nt = 0; nt < 4; ++nt) {
                int row = ms * 32 + mt * 16 + fr;
                int e = nh * 32 + nt * 8 + fc * 2;
                *(float2*)&lg[row * LGS + e] = make_float2(
                    fmaf(acc2[mt][nt][0], LO_INV, acc1[mt][nt][0]),
                    fmaf(acc2[mt][nt][1], LO_INV, acc1[mt][nt][1]));
                *(float2*)&lg[(row + 8) * LGS + e] = make_float2(
                    fmaf(acc2[mt][nt][2], LO_INV, acc1[mt][nt][2]),
                    fmaf(acc2[mt][nt][3], LO_INV, acc1[mt][nt][3]));
            }
    }
    __syncthreads();
    if (kg == 0) {
#pragma unroll
        for (int mt = 0; mt < 2; ++mt)
#pragma unroll
            for (int nt = 0; nt < 4; ++nt) {
                int row = ms * 32 + mt * 16 + fr;
                int e = nh * 32 + nt * 8 + fc * 2;
                float2 bv = *(const float2*)&sbias[e];
                float2 o0 = *(float2*)&lg[row * LGS + e];
                o0.x += fmaf(acc2[mt][nt][0], LO_INV, acc1[mt][nt][0]) + bv.x;
                o0.y += fmaf(acc2[mt][nt][1], LO_INV, acc1[mt][nt][1]) + bv.y;
                *(float2*)&lg[row * LGS + e] = o0;
                float2 o1 = *(float2*)&lg[(row + 8) * LGS + e];
                o1.x += fmaf(acc2[mt][nt][2], LO_INV, acc1[mt][nt][2]) + bv.x;
                o1.y += fmaf(acc2[mt][nt][3], LO_INV, acc1[mt][nt][3]) + bv.y;
                *(float2*)&lg[(row + 8) * LGS + e] = o1;
            }
    }
    __syncthreads();

    // ---- routing epilogue (identical to the passing kernels) ----
    if (tid < BM) {
        float* lrow = &lg[tid * LGS];
        float* orow = out + (size_t)(blockRow + tid) * NEXP;

        if (!anyImm) {
            float v1 = -3.4e38f, v2 = -3.4e38f;
            int i1 = 0, i2 = 0;
#pragma unroll
            for (int e = 0; e < NEXP; ++e) {
                float v = lrow[e];
                if (v > v1) { v2 = v1; i2 = i1; v1 = v; i1 = e; }
                else if (v > v2) { v2 = v; i2 = e; }
            }
            float t = __expf(v2 - v1);
            float inv = 1.0f / (1.0f + t);
            float4 z = make_float4(0.f, 0.f, 0.f, 0.f);
#pragma unroll
            for (int j = 0; j < NEXP / 4; ++j) ((float4*)orow)[j] = z;
            orow[i1] = inv;
            orow[i2] = t * inv;
        } else {
            float mx = -3.4e38f;
#pragma unroll
            for (int e = 0; e < NEXP; ++e) mx = fmaxf(mx, lrow[e]);
            float sum = 0.f;
#pragma unroll
            for (int e = 0; e < NEXP; ++e) {
                float t = __expf((lrow[e] - mx) * TEMP_INV);
                lrow[e] = t;
                sum += t;
            }
            float inv = 1.0f / sum;
#pragma unroll
            for (int e = 0; e < NEXP; ++e) orow[e] = lrow[e] * inv;
        }
    }
}

extern "C" void kernel_launch(void* const* d_in, const int* in_sizes, int n_in,
                              void* d_out, int out_size) {
    const float* x  = (const float*)d_in[0];
    const float* gw = (const float*)d_in[1];
    const float* gb = (const float*)d_in[2];
    const int*   mt = (const int*)d_in[3];
    float* out = (float*)d_out;

    const int M = in_sizes[0] / KD;     // 16384
    pack_w_kernel<<<128, 256>>>(gw);
    router_fp16<<<M / BM, 512>>>(x, gb, mt, out);
}